// round 16
// baseline (speedup 1.0000x reference)
#include <cuda_runtime.h>

// ---------------------------------------------------------------------------
// GCN 5-layer forward on GB300.
// Single-pass bucketed CSR: g_rows[col*CAP + slot], slot = atomicAdd(deg).
// k_pad fills bucket tails up to the next multiple of 16 with phantom node NN
// whose feature row is permanently zero -> gather needs NO masks.
// Hot chain: k_fused, 8 nodes/warp, W register-resident as 16 packed f32x2
// pairs. Gather: unpredicated 16-edge batches, ulonglong2 loads, packed
// add.rn.f32x2 accumulate. Epilogue: butterfly + STS.128 + 8 LDS.128 +
// 16 packed fma.rn.f32x2 matvec.
// ---------------------------------------------------------------------------

#define NN 100000
#define NE 1600000
#define CAP 64                  // bucket capacity (max degree ~50, P(>64)~1e-13)
#define NPW 8                   // nodes per warp in k_fused

__device__ int   g_deg[NN];               // edge in-degree (without self loop)
__device__ __align__(16) int g_rows[NN * CAP];  // bucketed CSR rows
__device__ float g_bufA[(NN + 1) * 32];   // +1 phantom zero row (never written)
__device__ float g_bufB[(NN + 1) * 32];
__device__ int   g_is64;                  // 1 if edge_index is int64

// ---- f32x2 packed helpers (sm_103a) ----
__device__ __forceinline__ unsigned long long f2add(unsigned long long a,
                                                    unsigned long long b) {
    unsigned long long d;
    asm("add.rn.f32x2 %0, %1, %2;" : "=l"(d) : "l"(a), "l"(b));
    return d;
}
__device__ __forceinline__ unsigned long long f2fma(unsigned long long a,
                                                    unsigned long long b,
                                                    unsigned long long c) {
    unsigned long long d;
    asm("fma.rn.f32x2 %0, %1, %2, %3;" : "=l"(d) : "l"(a), "l"(b), "l"(c));
    return d;
}
__device__ __forceinline__ unsigned long long f2pack(float a, float b) {
    unsigned long long d;
    asm("mov.b64 %0, {%1, %2};" : "=l"(d)
        : "r"(__float_as_uint(a)), "r"(__float_as_uint(b)));
    return d;
}
__device__ __forceinline__ float2 f2unpack(unsigned long long v) {
    unsigned lo, hi;
    asm("mov.b64 {%0, %1}, %2;" : "=r"(lo), "=r"(hi) : "l"(v));
    return make_float2(__uint_as_float(lo), __uint_as_float(hi));
}

// Zero degrees, probe edge dtype.
__global__ void k_zero(const long long* __restrict__ ei) {
    int i = blockIdx.x * blockDim.x + threadIdx.x;
    if (i < NN) g_deg[i] = 0;
    if (blockIdx.x == 0) {
        __shared__ int bad;
        if (threadIdx.x == 0) bad = 0;
        __syncthreads();
        long long v = ei[threadIdx.x];
        if (v < 0 || v >= NN) bad = 1;
        __syncthreads();
        if (threadIdx.x == 0) g_is64 = bad ? 0 : 1;
    }
}

// Single-pass bucketed CSR build.
__global__ void k_build(const int* __restrict__ ei32) {
    int i = blockIdx.x * blockDim.x + threadIdx.x;
    if (i >= NE) return;
    int is64 = g_is64;
    int r = is64 ? ei32[2 * i] : ei32[i];
    int c = is64 ? ei32[2 * (NE + i)] : ei32[NE + i];
    if ((unsigned)c < NN && (unsigned)r < NN) {
        int s = atomicAdd(&g_deg[c], 1);
        if (s < CAP) g_rows[c * CAP + s] = r;
    }
}

// Fill bucket tails [cnt, ceil16(cnt)) with phantom node NN (zero row).
__global__ void k_pad() {
    int i = blockIdx.x * blockDim.x + threadIdx.x;
    if (i >= NN * 16) return;
    int node = i >> 4;
    int j    = i & 15;
    int cnt  = min(g_deg[node], CAP);
    int s    = cnt + j;
    if (s < ((cnt + 15) & ~15)) g_rows[node * CAP + s] = NN;
}

// transform1: g_bufA = dinv * (x @ W1), 8 -> 32. Warp per node.
__global__ void k_t1(const float* __restrict__ x, const float* __restrict__ W1) {
    __shared__ float sW[8 * 32];
    for (int i = threadIdx.x; i < 8 * 32; i += blockDim.x) sW[i] = W1[i];
    __syncthreads();

    int node = (blockIdx.x * blockDim.x + threadIdx.x) >> 5;
    int lane = threadIdx.x & 31;
    if (node >= NN) return;

    float hv = (lane < 8) ? x[node * 8 + lane] : 0.f;
    float acc = 0.f;
#pragma unroll
    for (int k = 0; k < 8; ++k)
        acc += __shfl_sync(0xffffffffu, hv, k) * sW[k * 32 + lane];
    float dinv = rsqrtf((float)(g_deg[node] + 1));
    g_bufA[node * 32 + lane] = acc * dinv;
}

// Fused: per warp, NPW consecutive nodes. Unpredicated 16-edge batches over
// zero-padded buckets; packed-f32x2 accumulate and matvec.
template <int DNEXT, int OS, bool AtoB>
__global__ __launch_bounds__(128)
void k_fused(const float* __restrict__ bias, const float* __restrict__ W) {
    const float* gsrc = AtoB ? g_bufA : g_bufB;
    float*       gdst = AtoB ? g_bufB : g_bufA;

    __shared__ float4 sh_h[4][8];      // per-warp h row (32 floats)

    int wid   = (blockIdx.x * blockDim.x + threadIdx.x) >> 5;
    int wloc  = threadIdx.x >> 5;
    int lane  = threadIdx.x & 31;
    int node0 = wid * NPW;
    if (node0 >= NN) return;

    // W packed as 16 f32x2 pairs: Wp[j] = (W[2j][lane], W[2j+1][lane]).
    unsigned long long Wp[16];
#pragma unroll
    for (int k = 0; k < 16; ++k) {
        float wa = (lane < DNEXT) ? W[(2 * k) * DNEXT + lane] : 0.f;
        float wb = (lane < DNEXT) ? W[(2 * k + 1) * DNEXT + lane] : 0.f;
        Wp[k] = f2pack(wa, wb);
    }

    int grp = lane >> 3;              // which edge of the 4-edge pack
    int fl  = lane & 7;               // 16B column within the 128B row
    float4 bias4 = ((const float4*)bias)[fl];

    int mydeg = 0;
    if (lane < NPW) mydeg = min(g_deg[node0 + lane], CAP);

    const ulonglong2* s2    = (const ulonglong2*)gsrc;
    const int4*       rows4 = (const int4*)g_rows;
    const ulonglong2* shp   = (const ulonglong2*)&sh_h[wloc][0];

#pragma unroll 1
    for (int n = 0; n < NPW; ++n) {
        int node = node0 + n;
        int cnt  = __shfl_sync(0xffffffffu, mydeg, n);

        // Self-loop term contributed once by group 0.
        unsigned long long alo = 0ull, ahi = 0ull;
        if (grp == 0) {
            ulonglong2 sv = s2[node * 8 + fl];
            alo = sv.x; ahi = sv.y;
        }

        if (cnt > 0) {
            int nb = (cnt + 15) >> 4;             // batches of 16 edges
            int q  = node * (CAP / 4) + grp;      // int4 slot for this group
#pragma unroll 1
            for (int b = 0; b < nb; ++b) {
                int4 r = rows4[q];                // 4 indices, one LDG.128
                q += 4;
                ulonglong2 v0 = s2[r.x * 8 + fl];
                ulonglong2 v1 = s2[r.y * 8 + fl];
                ulonglong2 v2 = s2[r.z * 8 + fl];
                ulonglong2 v3 = s2[r.w * 8 + fl];
                alo = f2add(alo, f2add(f2add(v0.x, v1.x), f2add(v2.x, v3.x)));
                ahi = f2add(ahi, f2add(f2add(v0.y, v1.y), f2add(v2.y, v3.y)));
            }
        }

        // Unpack and butterfly across the 4 groups.
        float2 plo = f2unpack(alo);
        float2 phi = f2unpack(ahi);
        float ax = plo.x, ay = plo.y, az = phi.x, aw = phi.y;
#pragma unroll
        for (int d = 8; d <= 16; d <<= 1) {
            ax += __shfl_xor_sync(0xffffffffu, ax, d);
            ay += __shfl_xor_sync(0xffffffffu, ay, d);
            az += __shfl_xor_sync(0xffffffffu, az, d);
            aw += __shfl_xor_sync(0xffffffffu, aw, d);
        }

        float dinv = rsqrtf((float)(cnt + 1));
        float4 h4;
        h4.x = ax * dinv + bias4.x;
        h4.y = ay * dinv + bias4.y;
        h4.z = az * dinv + bias4.z;
        h4.w = aw * dinv + bias4.w;

        if (grp == 0) sh_h[wloc][fl] = h4;    // one STS.128 per fl
        __syncwarp();

        // Matvec: 8 LDS.128 + 16 packed FFMA against register W pairs.
        unsigned long long apair = 0ull;
#pragma unroll
        for (int c = 0; c < 8; ++c) {
            ulonglong2 hp = shp[c];
            apair = f2fma(hp.x, Wp[2 * c], apair);
            apair = f2fma(hp.y, Wp[2 * c + 1], apair);
        }
        float2 af = f2unpack(apair);
        float a2 = af.x + af.y;
        __syncwarp();                          // before next node overwrites

        if (lane < DNEXT) gdst[node * OS + lane] = a2 * dinv;
    }
}

// Final aggregation over stride-4 rows in g_bufA (dout=3): 1 lane per edge.
__global__ void k_final(float* __restrict__ out,
                        const float* __restrict__ bias) {
    int warp = (blockIdx.x * blockDim.x + threadIdx.x) >> 5;
    int lane = threadIdx.x & 31;
    if (warp >= NN) return;

    int cnt   = min(g_deg[warp], CAP);
    int start = warp * CAP;
    int end   = start + cnt;

    const float4* src4 = (const float4*)g_bufA;
    float4 acc = make_float4(0.f, 0.f, 0.f, 0.f);
    if (lane == 0) {                           // self loop
        float4 v = src4[warp];
        acc.x = v.x; acc.y = v.y; acc.z = v.z;
    }

    for (int e = start + lane; e < end; e += 32) {
        int r = g_rows[e];
        float4 v = src4[r];
        acc.x += v.x; acc.y += v.y; acc.z += v.z;
    }
#pragma unroll
    for (int d = 1; d <= 16; d <<= 1) {
        acc.x += __shfl_xor_sync(0xffffffffu, acc.x, d);
        acc.y += __shfl_xor_sync(0xffffffffu, acc.y, d);
        acc.z += __shfl_xor_sync(0xffffffffu, acc.z, d);
    }
    if (lane == 0) {
        float dinv = rsqrtf((float)(cnt + 1));
        out[warp * 3 + 0] = acc.x * dinv + bias[0];
        out[warp * 3 + 1] = acc.y * dinv + bias[1];
        out[warp * 3 + 2] = acc.z * dinv + bias[2];
    }
}

extern "C" void kernel_launch(void* const* d_in, const int* in_sizes, int n_in,
                              void* d_out, int out_size) {
    const float* x    = (const float*)d_in[0];
    const int*   ei32 = (const int*)d_in[1];
    const float* W1 = (const float*)d_in[2];
    const float* b1 = (const float*)d_in[3];
    const float* W2 = (const float*)d_in[4];
    const float* b2 = (const float*)d_in[5];
    const float* W3 = (const float*)d_in[6];
    const float* b3 = (const float*)d_in[7];
    const float* W4 = (const float*)d_in[8];
    const float* b4 = (const float*)d_in[9];
    const float* W5 = (const float*)d_in[10];
    const float* b5 = (const float*)d_in[11];

    const int TB = 256;
    dim3 nodeGrid((NN + TB - 1) / TB);
    dim3 edgeGrid((NE + TB - 1) / TB);
    dim3 padGrid((NN * 16 + TB - 1) / TB);
    dim3 warpGrid((NN * 32 + TB - 1) / TB);              // warp per node
    const int nwarps = (NN + NPW - 1) / NPW;             // k_fused warps
    const int FTB = 128;
    dim3 fusedGrid((nwarps * 32 + FTB - 1) / FTB);

    k_zero<<<nodeGrid, TB>>>((const long long*)ei32);     // 0
    k_build<<<edgeGrid, TB>>>(ei32);                      // 1: bucketed CSR
    k_pad<<<padGrid, TB>>>();                             // 2: zero-row padding
    k_t1<<<warpGrid, TB>>>(x, W1);                        // 3: x -> A
    k_fused<32, 32, true ><<<fusedGrid, FTB>>>(b1, W2);   // 4: A -> B
    k_fused<32, 32, false><<<fusedGrid, FTB>>>(b2, W3);   // 5: B -> A
    k_fused<32, 32, true ><<<fusedGrid, FTB>>>(b3, W4);   // 6: A -> B
    k_fused<3, 4, false><<<fusedGrid, FTB>>>(b4, W5);     // 7: B -> A (stride 4)
    k_final<<<warpGrid, TB>>>((float*)d_out, b5);         // 8
}

// round 17
// speedup vs baseline: 1.0893x; 1.0893x over previous
#include <cuda_runtime.h>

// ---------------------------------------------------------------------------
// GCN 5-layer forward on GB300.
// Single-pass bucketed CSR: g_rows[col*CAP + slot], slot = atomicAdd(deg).
// k_pad fills bucket tails up to the next multiple of 16 with phantom node NN
// whose feature row is permanently zero -> gather is MASKLESS (round-15
// scalar float4 datapath, minus all tail predication).
// Hot chain: k_fused, 8 nodes/warp, register-resident W, unpredicated
// 16-edge int4-index batches, butterfly + STS.128 + broadcast LDS.128 matvec.
// (f32x2 packed datapath from round 16 reverted: 64-bit reg pairing + pack/
// unpack glue cost more than the saved FADDs on this latency-bound kernel.)
// ---------------------------------------------------------------------------

#define NN 100000
#define NE 1600000
#define CAP 64                  // bucket capacity (max degree ~50, P(>64)~1e-13)
#define NPW 8                   // nodes per warp in k_fused

__device__ int   g_deg[NN];               // edge in-degree (without self loop)
__device__ __align__(16) int g_rows[NN * CAP];  // bucketed CSR rows
__device__ float g_bufA[(NN + 1) * 32];   // +1 phantom zero row (never written)
__device__ float g_bufB[(NN + 1) * 32];
__device__ int   g_is64;                  // 1 if edge_index is int64

// Zero degrees, probe edge dtype.
__global__ void k_zero(const long long* __restrict__ ei) {
    int i = blockIdx.x * blockDim.x + threadIdx.x;
    if (i < NN) g_deg[i] = 0;
    if (blockIdx.x == 0) {
        __shared__ int bad;
        if (threadIdx.x == 0) bad = 0;
        __syncthreads();
        long long v = ei[threadIdx.x];
        if (v < 0 || v >= NN) bad = 1;
        __syncthreads();
        if (threadIdx.x == 0) g_is64 = bad ? 0 : 1;
    }
}

// Single-pass bucketed CSR build.
__global__ void k_build(const int* __restrict__ ei32) {
    int i = blockIdx.x * blockDim.x + threadIdx.x;
    if (i >= NE) return;
    int is64 = g_is64;
    int r = is64 ? ei32[2 * i] : ei32[i];
    int c = is64 ? ei32[2 * (NE + i)] : ei32[NE + i];
    if ((unsigned)c < NN && (unsigned)r < NN) {
        int s = atomicAdd(&g_deg[c], 1);
        if (s < CAP) g_rows[c * CAP + s] = r;
    }
}

// Fill bucket tails [cnt, ceil16(cnt)) with phantom node NN (zero row).
__global__ void k_pad() {
    int i = blockIdx.x * blockDim.x + threadIdx.x;
    if (i >= NN * 16) return;
    int node = i >> 4;
    int j    = i & 15;
    int cnt  = min(g_deg[node], CAP);
    int s    = cnt + j;
    if (s < ((cnt + 15) & ~15)) g_rows[node * CAP + s] = NN;
}

// transform1: g_bufA = dinv * (x @ W1), 8 -> 32. Warp per node.
__global__ void k_t1(const float* __restrict__ x, const float* __restrict__ W1) {
    __shared__ float sW[8 * 32];
    for (int i = threadIdx.x; i < 8 * 32; i += blockDim.x) sW[i] = W1[i];
    __syncthreads();

    int node = (blockIdx.x * blockDim.x + threadIdx.x) >> 5;
    int lane = threadIdx.x & 31;
    if (node >= NN) return;

    float hv = (lane < 8) ? x[node * 8 + lane] : 0.f;
    float acc = 0.f;
#pragma unroll
    for (int k = 0; k < 8; ++k)
        acc += __shfl_sync(0xffffffffu, hv, k) * sW[k * 32 + lane];
    float dinv = rsqrtf((float)(g_deg[node] + 1));
    g_bufA[node * 32 + lane] = acc * dinv;
}

// Fused: per warp, NPW consecutive nodes. Maskless 16-edge batches over
// zero-padded buckets; then g2 = dinv*(h @ W), W register-resident.
template <int DNEXT, int OS, bool AtoB>
__global__ __launch_bounds__(128)
void k_fused(const float* __restrict__ bias, const float* __restrict__ W) {
    const float* gsrc = AtoB ? g_bufA : g_bufB;
    float*       gdst = AtoB ? g_bufB : g_bufA;

    __shared__ float4 sh_h[4][8];      // per-warp h row (32 floats)

    int wid   = (blockIdx.x * blockDim.x + threadIdx.x) >> 5;
    int wloc  = threadIdx.x >> 5;
    int lane  = threadIdx.x & 31;
    int node0 = wid * NPW;
    if (node0 >= NN) return;

    // W[k][lane] into registers, once per warp (amortized over NPW nodes).
    float Wr[32];
#pragma unroll
    for (int k = 0; k < 32; ++k)
        Wr[k] = (lane < DNEXT) ? W[k * DNEXT + lane] : 0.f;

    int grp = lane >> 3;              // which edge of the 4-edge pack
    int fl  = lane & 7;               // float4 column within the row
    float4 bias4 = ((const float4*)bias)[fl];

    // Prefetch degrees for the NPW nodes (1 coalesced load).
    int mydeg = 0;
    if (lane < NPW) mydeg = min(g_deg[node0 + lane], CAP);

    const float4* src4  = (const float4*)gsrc;
    const int4*   rows4 = (const int4*)g_rows;

#pragma unroll 1
    for (int n = 0; n < NPW; ++n) {
        int node = node0 + n;
        int cnt  = __shfl_sync(0xffffffffu, mydeg, n);

        // Self-loop term contributed once by group 0.
        float4 acc = make_float4(0.f, 0.f, 0.f, 0.f);
        if (grp == 0) acc = src4[node * 8 + fl];

        if (cnt > 0) {
            int nb = (cnt + 15) >> 4;             // batches of 16 edges
            int q  = node * (CAP / 4) + grp;      // int4 slot for this group
#pragma unroll 1
            for (int b = 0; b < nb; ++b) {
                int4 r = rows4[q];                // 4 indices, one LDG.128
                q += 4;
                float4 v0 = src4[r.x * 8 + fl];   // pad edges hit zero row
                float4 v1 = src4[r.y * 8 + fl];
                float4 v2 = src4[r.z * 8 + fl];
                float4 v3 = src4[r.w * 8 + fl];
                acc.x += (v0.x + v1.x) + (v2.x + v3.x);
                acc.y += (v0.y + v1.y) + (v2.y + v3.y);
                acc.z += (v0.z + v1.z) + (v2.z + v3.z);
                acc.w += (v0.w + v1.w) + (v2.w + v3.w);
            }
        }

        // Butterfly across the 4 groups: all lanes hold the column sums.
#pragma unroll
        for (int d = 8; d <= 16; d <<= 1) {
            acc.x += __shfl_xor_sync(0xffffffffu, acc.x, d);
            acc.y += __shfl_xor_sync(0xffffffffu, acc.y, d);
            acc.z += __shfl_xor_sync(0xffffffffu, acc.z, d);
            acc.w += __shfl_xor_sync(0xffffffffu, acc.w, d);
        }

        float dinv = rsqrtf((float)(cnt + 1));
        float4 h4;
        h4.x = acc.x * dinv + bias4.x;
        h4.y = acc.y * dinv + bias4.y;
        h4.z = acc.z * dinv + bias4.z;
        h4.w = acc.w * dinv + bias4.w;

        if (grp == 0) sh_h[wloc][fl] = h4;    // one STS.128 per fl
        __syncwarp();

        // Matvec: 8 broadcast LDS.128 + 32 FFMA against register W.
        float a2 = 0.f;
#pragma unroll
        for (int c = 0; c < 8; ++c) {
            float4 hc = sh_h[wloc][c];
            a2 += hc.x * Wr[4 * c] + hc.y * Wr[4 * c + 1]
                + hc.z * Wr[4 * c + 2] + hc.w * Wr[4 * c + 3];
        }
        __syncwarp();                          // before next node overwrites

        if (lane < DNEXT) gdst[node * OS + lane] = a2 * dinv;
    }
}

// Final aggregation over stride-4 rows in g_bufA (dout=3): 1 lane per edge.
__global__ void k_final(float* __restrict__ out,
                        const float* __restrict__ bias) {
    int warp = (blockIdx.x * blockDim.x + threadIdx.x) >> 5;
    int lane = threadIdx.x & 31;
    if (warp >= NN) return;

    int cnt   = min(g_deg[warp], CAP);
    int start = warp * CAP;
    int end   = start + cnt;

    const float4* src4 = (const float4*)g_bufA;
    float4 acc = make_float4(0.f, 0.f, 0.f, 0.f);
    if (lane == 0) {                           // self loop
        float4 v = src4[warp];
        acc.x = v.x; acc.y = v.y; acc.z = v.z;
    }

    for (int e = start + lane; e < end; e += 32) {
        int r = g_rows[e];
        float4 v = src4[r];
        acc.x += v.x; acc.y += v.y; acc.z += v.z;
    }
#pragma unroll
    for (int d = 1; d <= 16; d <<= 1) {
        acc.x += __shfl_xor_sync(0xffffffffu, acc.x, d);
        acc.y += __shfl_xor_sync(0xffffffffu, acc.y, d);
        acc.z += __shfl_xor_sync(0xffffffffu, acc.z, d);
    }
    if (lane == 0) {
        float dinv = rsqrtf((float)(cnt + 1));
        out[warp * 3 + 0] = acc.x * dinv + bias[0];
        out[warp * 3 + 1] = acc.y * dinv + bias[1];
        out[warp * 3 + 2] = acc.z * dinv + bias[2];
    }
}

extern "C" void kernel_launch(void* const* d_in, const int* in_sizes, int n_in,
                              void* d_out, int out_size) {
    const float* x    = (const float*)d_in[0];
    const int*   ei32 = (const int*)d_in[1];
    const float* W1 = (const float*)d_in[2];
    const float* b1 = (const float*)d_in[3];
    const float* W2 = (const float*)d_in[4];
    const float* b2 = (const float*)d_in[5];
    const float* W3 = (const float*)d_in[6];
    const float* b3 = (const float*)d_in[7];
    const float* W4 = (const float*)d_in[8];
    const float* b4 = (const float*)d_in[9];
    const float* W5 = (const float*)d_in[10];
    const float* b5 = (const float*)d_in[11];

    const int TB = 256;
    dim3 nodeGrid((NN + TB - 1) / TB);
    dim3 edgeGrid((NE + TB - 1) / TB);
    dim3 padGrid((NN * 16 + TB - 1) / TB);
    dim3 warpGrid((NN * 32 + TB - 1) / TB);              // warp per node
    const int nwarps = (NN + NPW - 1) / NPW;             // k_fused warps
    const int FTB = 128;
    dim3 fusedGrid((nwarps * 32 + FTB - 1) / FTB);

    k_zero<<<nodeGrid, TB>>>((const long long*)ei32);     // 0
    k_build<<<edgeGrid, TB>>>(ei32);                      // 1: bucketed CSR
    k_pad<<<padGrid, TB>>>();                             // 2: zero-row padding
    k_t1<<<warpGrid, TB>>>(x, W1);                        // 3: x -> A
    k_fused<32, 32, true ><<<fusedGrid, FTB>>>(b1, W2);   // 4: A -> B
    k_fused<32, 32, false><<<fusedGrid, FTB>>>(b2, W3);   // 5: B -> A
    k_fused<32, 32, true ><<<fusedGrid, FTB>>>(b3, W4);   // 6: A -> B
    k_fused<3, 4, false><<<fusedGrid, FTB>>>(b4, W5);     // 7: B -> A (stride 4)
    k_final<<<warpGrid, TB>>>((float*)d_out, b5);         // 8
}